// round 7
// baseline (speedup 1.0000x reference)
#include <cuda_runtime.h>

#define NN 25000
#define NE 400000

#define INV_SQRT3 0.57735026919f
#define INV_SQRT2 0.70710678119f

// ---------------- scratch (device globals; allocation-free) ----------------
__device__ float4 d_g_s  [NN * 16];   // s   = s_in @ W1_0 /8           (N,64)
__device__ float4 d_g_v  [NN * 24];   // v   = v_in . W1_1 /sqrt32      (N,32,3) [u*3+c]
__device__ float4 d_g_scs[NN * 16];   // sc_s                           (N,64)
__device__ float4 d_g_scv[NN * 24];   // sc_v                           (N,96)  [u*3+c]
__device__ float4 d_g_ns [NN * 24];   // scatter accum s-part           (N,96)
__device__ float4 d_g_nv [NN * 96];   // scatter accum v-part           (N,3,128) [c][u]
__device__ float  d_W1T[64 * 8];      // Wfc1^T [k][m], prescaled 1/sqrt(8)
__device__ float  d_W2K[64 * 64];     // Wfc2 k-major [k][j], prescaled 1/8
__device__ float  d_W3T[224 * 64];    // Wfc3^T [j][k], prescaled WS (+INV_SQRT3/2)

// ---------------- f32x2 helpers ----------------
#define FMA2(d, a, b) \
    asm("fma.rn.f32x2 %0, %1, %2, %0;" : "+l"(d) : "l"(a), "l"(b))
#define ADD2(d, a, b) \
    asm("add.rn.f32x2 %0, %1, %2;" : "=l"(d) : "l"(a), "l"(b))
#define PACK2(d, lo, hi) \
    asm("mov.b64 %0, {%1, %2};" : "=l"(d) : "f"(lo), "f"(hi))
#define UNPACK2(lo, hi, s) \
    asm("mov.b64 {%0, %1}, %2;" : "=f"(lo), "=f"(hi) : "l"(s))

__device__ __forceinline__ float silu_f(float x) {
    return x / (1.0f + __expf(-x));
}

// dot of 64 floats: h packed as 32 f32x2 pairs, w = 16B-aligned smem row
__device__ __forceinline__ float dot64x2(const unsigned long long* h,
                                         const float* w) {
    unsigned long long a0 = 0ull, a1 = 0ull, a2 = 0ull, a3 = 0ull;
    const ulonglong2* q = reinterpret_cast<const ulonglong2*>(w);
#pragma unroll
    for (int k = 0; k < 8; ++k) {
        ulonglong2 w0 = q[2 * k];
        ulonglong2 w1 = q[2 * k + 1];
        FMA2(a0, h[4 * k + 0], w0.x);
        FMA2(a1, h[4 * k + 1], w0.y);
        FMA2(a2, h[4 * k + 2], w1.x);
        FMA2(a3, h[4 * k + 3], w1.y);
    }
    ADD2(a0, a0, a1);
    ADD2(a2, a2, a3);
    ADD2(a0, a0, a2);
    float lo, hi;
    UNPACK2(lo, hi, a0);
    return lo + hi;
}

__device__ __forceinline__ void red4(float* p, float a, float b, float c, float d) {
    asm volatile("red.global.add.v4.f32 [%0], {%1,%2,%3,%4};"
                 :: "l"(p), "f"(a), "f"(b), "f"(c), "f"(d) : "memory");
}

// ---------------- kernel 0: zero accumulators + transpose/prescale weights ---
__global__ void k_pre(const float* __restrict__ Wfc1,
                      const float* __restrict__ Wfc2,
                      const float* __restrict__ Wfc3) {
    int i = blockIdx.x * 256 + threadIdx.x;
    const int NZ = NN * 120;   // float4 count of (ns + nv)
    if (i < NZ) {
        float4 z = make_float4(0.f, 0.f, 0.f, 0.f);
        if (i < NN * 24) d_g_ns[i] = z;
        else             d_g_nv[i - NN * 24] = z;
    } else {
        int j = i - NZ;
        if (j < 512) {
            d_W1T[j] = Wfc1[(j & 7) * 64 + (j >> 3)] * 0.3535533906f;
        } else if (j < 512 + 4096) {
            int k = j - 512;
            d_W2K[k] = Wfc2[k] * 0.125f;     // already k-major
        } else if (j < 512 + 4096 + 14336) {
            int k = j - 4608;
            int row = k >> 6;
            float s = 0.03125f;  // (1/sqrt(64)) * (1/sqrt(16))
            if (row >= 192)      s *= INV_SQRT2;
            else if (row >= 160) s *= INV_SQRT3;
            d_W3T[k] = Wfc3[(k & 63) * 224 + row] * s;
        }
    }
}

// ---------------- kernel 2: node prep, persistent warp-per-node ----------------
__global__ void __launch_bounds__(256) k_prep(const float* __restrict__ nh,
                                              const float* __restrict__ W1_0,
                                              const float* __restrict__ W1_1,
                                              const float* __restrict__ Wsc0,
                                              const float* __restrict__ Wsc1) {
    __shared__ float sW10[4096], sWsc0[4096], sW11[1024], sWsc1[1024], sIn[1280];
    int t = threadIdx.x;
    for (int i = t; i < 4096; i += 256) { sW10[i] = W1_0[i]; sWsc0[i] = Wsc0[i]; }
    for (int i = t; i < 1024; i += 256) { sW11[i] = W1_1[i]; sWsc1[i] = Wsc1[i]; }
    __syncthreads();

    int wid = t >> 5, l = t & 31;
    float* gs  = (float*)d_g_s;
    float* gv  = (float*)d_g_v;
    float* gss = (float*)d_g_scs;
    float* gsv = (float*)d_g_scv;
    float* row = sIn + wid * 160;

    for (int it = 0; it < 8; ++it) {
        int n = blockIdx.x * 64 + it * 8 + wid;
        if (n >= NN) break;
        {
            const float4* src = reinterpret_cast<const float4*>(nh + (size_t)n * 160);
            float4* dst = reinterpret_cast<float4*>(row);
            for (int i = l; i < 40; i += 32) dst[i] = __ldg(src + i);
        }
        __syncwarp();
#pragma unroll
        for (int r = 0; r < 2; ++r) {
            int o = l + r * 32;
            float a = 0.f, b = 0.f;
#pragma unroll 8
            for (int u = 0; u < 64; ++u) {
                float x = row[u];
                a += x * sW10[u * 64 + o];
                b += x * sWsc0[u * 64 + o];
            }
            gs [(size_t)n * 64 + o] = a * 0.125f;
            gss[(size_t)n * 64 + o] = b * 0.125f;
        }
#pragma unroll
        for (int r = 0; r < 3; ++r) {
            int o = l + r * 32;
            int up = o / 3, c = o - up * 3;
            float a = 0.f, b = 0.f;
#pragma unroll 8
            for (int u = 0; u < 32; ++u) {
                float x = row[64 + u * 3 + c];
                a += x * sW11[u * 32 + up];
                b += x * sWsc1[u * 32 + up];
            }
            gv [(size_t)n * 96 + o] = a * 0.1767766953f;
            gsv[(size_t)n * 96 + o] = b * 0.1767766953f;
        }
        __syncwarp();
    }
}

// ---------------- kernel 3: edge MLP + messages + scatter ----------------
// Phased smem: [sW2K | sW1] live only during the MLP phase, then the same
// region is overwritten with sW3 for the w-phase. 57344 B total.
__global__ void __launch_bounds__(128, 4) k_edge(const int* __restrict__ ei,
                                                 const float* __restrict__ esh,
                                                 const float* __restrict__ eattr) {
    extern __shared__ float sm[];
    float* sW2K = sm;          // 4096 floats  [k][j] (phase 1)
    float* sW1  = sm + 4096;   // 512 floats   [k][m] (phase 1)
    float* sW3  = sm;          // 14336 floats [j][k] (phase 2)
    int t = threadIdx.x;
    for (int i = t; i < 4096; i += 128) sW2K[i] = d_W2K[i];
    for (int i = t; i < 512;  i += 128) sW1[i]  = d_W1T[i];
    __syncthreads();

    int e = blockIdx.x * 128 + t;   // NE = 3125*128 exactly

    // ---- edge MLP, k-outer: h1[k] computed just-in-time, h1 never stored ----
    float att0, att1, att2, att3, att4, att5, att6, att7;
    {
        const float4* ap = reinterpret_cast<const float4*>(eattr + (size_t)e * 8);
        float4 a0 = __ldg(ap), a1 = __ldg(ap + 1);
        att0 = a0.x; att1 = a0.y; att2 = a0.z; att3 = a0.w;
        att4 = a1.x; att5 = a1.y; att6 = a1.z; att7 = a1.w;
    }
    unsigned long long h2p[32];
#pragma unroll
    for (int p = 0; p < 32; ++p) h2p[p] = 0ull;
#pragma unroll 4
    for (int k = 0; k < 64; ++k) {
        float4 q0 = *reinterpret_cast<const float4*>(sW1 + k * 8);
        float4 q1 = *reinterpret_cast<const float4*>(sW1 + k * 8 + 4);
        float a = att0 * q0.x + att1 * q0.y + att2 * q0.z + att3 * q0.w
                + att4 * q1.x + att5 * q1.y + att6 * q1.z + att7 * q1.w;
        float h = silu_f(a);
        unsigned long long hkk;
        PACK2(hkk, h, h);
        const ulonglong2* q = reinterpret_cast<const ulonglong2*>(sW2K + k * 64);
#pragma unroll
        for (int i = 0; i < 16; ++i) {
            ulonglong2 ww = q[i];
            FMA2(h2p[2 * i],     hkk, ww.x);
            FMA2(h2p[2 * i + 1], hkk, ww.y);
        }
    }
#pragma unroll
    for (int p = 0; p < 32; ++p) {
        float lo, hi;
        UNPACK2(lo, hi, h2p[p]);
        PACK2(h2p[p], silu_f(lo), silu_f(hi));
    }

    __syncthreads();   // done reading sW1/sW2K
    for (int i = t; i < 14336; i += 128) sW3[i] = d_W3T[i];
    __syncthreads();

    int src = __ldg(ei + e);
    int dst = __ldg(ei + NE + e);
    float4 sh = __ldg(reinterpret_cast<const float4*>(esh + (size_t)e * 4));
    float sh0 = sh.x, shx = sh.y, shy = sh.z, shz = sh.w;

    const float* sd  = (const float*)d_g_s + (size_t)dst * 64;
    const float* vd  = (const float*)d_g_v + (size_t)dst * 96;
    float*       nsp = (float*)d_g_ns + (size_t)src * 96;
    float*       nvp = (float*)d_g_nv + (size_t)src * 384;

    // ---- m0 (ns[0:64]) and mv0 (nv[c][0:64]) ----
#pragma unroll 1
    for (int g = 0; g < 16; ++g) {
        float4 s4 = __ldg(reinterpret_cast<const float4*>(sd) + g);
        float sdl[4]  = {s4.x, s4.y, s4.z, s4.w};
        float sdl0[4] = {s4.x * sh0, s4.y * sh0, s4.z * sh0, s4.w * sh0};
        float m0[4], w1s[4];
#pragma unroll
        for (int i = 0; i < 4; ++i) {
            int j = g * 4 + i;
            float w0 = dot64x2(h2p, sW3 + j * 64);
            float w1 = dot64x2(h2p, sW3 + (64 + j) * 64);
            m0[i]  = w0 * sdl0[i];
            w1s[i] = w1 * sdl[i];
        }
        red4(nsp + g * 4, m0[0], m0[1], m0[2], m0[3]);
        red4(nvp +       g * 4, w1s[0] * shx, w1s[1] * shx, w1s[2] * shx, w1s[3] * shx);
        red4(nvp + 128 + g * 4, w1s[0] * shy, w1s[1] * shy, w1s[2] * shy, w1s[3] * shy);
        red4(nvp + 256 + g * 4, w1s[0] * shz, w1s[1] * shz, w1s[2] * shz, w1s[3] * shz);
    }

    // ---- m1 (ns[64:96]), mv1 (nv[c][64:96]), mv2 (nv[c][96:128]) ----
#pragma unroll 1
    for (int g = 0; g < 8; ++g) {
        const float4* vb = reinterpret_cast<const float4*>(vd + g * 12);
        float4 b0 = __ldg(vb), b1 = __ldg(vb + 1), b2 = __ldg(vb + 2);
        float vv[12] = {b0.x, b0.y, b0.z, b0.w, b1.x, b1.y, b1.z, b1.w,
                        b2.x, b2.y, b2.z, b2.w};
        float m1[4], mv1[3][4], mv2[3][4];
#pragma unroll
        for (int i = 0; i < 4; ++i) {
            int u = g * 4 + i;
            float w2 = dot64x2(h2p, sW3 + (128 + u) * 64);
            float w3 = dot64x2(h2p, sW3 + (160 + u) * 64);  // incl INV_SQRT3
            float w4 = dot64x2(h2p, sW3 + (192 + u) * 64);  // incl INV_SQRT2
            float vx = vv[i * 3], vy = vv[i * 3 + 1], vz = vv[i * 3 + 2];
            m1[i] = w3 * (vx * shx + vy * shy + vz * shz);
            mv1[0][i] = w2 * vx * sh0;
            mv1[1][i] = w2 * vy * sh0;
            mv1[2][i] = w2 * vz * sh0;
            mv2[0][i] = w4 * (vy * shz - vz * shy);
            mv2[1][i] = w4 * (vz * shx - vx * shz);
            mv2[2][i] = w4 * (vx * shy - vy * shx);
        }
        red4(nsp + 64 + g * 4, m1[0], m1[1], m1[2], m1[3]);
#pragma unroll
        for (int c = 0; c < 3; ++c) {
            red4(nvp + c * 128 + 64 + g * 4, mv1[c][0], mv1[c][1], mv1[c][2], mv1[c][3]);
            red4(nvp + c * 128 + 96 + g * 4, mv2[c][0], mv2[c][1], mv2[c][2], mv2[c][3]);
        }
    }
}

// ---------------- kernel 4: output projection + skip + RMS ----------------
// 4 nodes per warp: each weight LDS feeds 4 FMAs; acc reads are float4
// broadcasts. 391 blocks x 8 warps x 4 nodes x 2 iterations = 25024 >= NN.
// smem: 10368 + 8*1920 = 25728 floats = 102912 B (request 103040, padded).
__global__ void __launch_bounds__(256) k_out(float* __restrict__ out,
                                             const float* __restrict__ W2_0,
                                             const float* __restrict__ W2_1,
                                             const float* __restrict__ g0,
                                             const float* __restrict__ g1) {
    extern __shared__ float smo[];
    float* sW20 = smo;           // 6144
    float* sW21 = smo + 6144;    // 4096
    float* sG   = smo + 10240;   // 96 (g0 64 + g1 32) + 32 pad
    float* sAcc = smo + 10368;   // 8 warps * 4 nodes * 480 = 15360
    int t = threadIdx.x;
    for (int i = t; i < 6144; i += 256) sW20[i] = W2_0[i];
    for (int i = t; i < 4096; i += 256) sW21[i] = W2_1[i];
    if (t < 64) sG[t] = g0[t];
    else if (t < 96) sG[t] = g1[t - 64];
    __syncthreads();

    const float4* gns4 = d_g_ns;
    const float4* gnv4 = d_g_nv;
    const float* gss = (const float*)d_g_scs;
    const float* gsv = (const float*)d_g_scv;

    int wid = t >> 5, l = t & 31;
    float* acc = sAcc + wid * 1920;          // 4 nodes * 480

    for (int it = 0; it < 2; ++it) {
        int nb = blockIdx.x * 64 + it * 32 + wid * 4;

        // stage 4 nodes' accumulators (float4, coalesced broadcast source)
#pragma unroll
        for (int j = 0; j < 4; ++j) {
            int n = min(nb + j, NN - 1);
            float4* dst = reinterpret_cast<float4*>(acc + j * 480);
            for (int i = l; i < 120; i += 32)
                dst[i] = (i < 24) ? __ldg(gns4 + (size_t)n * 24 + i)
                                  : __ldg(gnv4 + (size_t)n * 96 + (i - 24));
        }
        __syncwarp();

        float as[2][4], av[3][4];
#pragma unroll
        for (int r = 0; r < 2; ++r)
#pragma unroll
            for (int j = 0; j < 4; ++j) as[r][j] = 0.f;
#pragma unroll
        for (int r = 0; r < 3; ++r)
#pragma unroll
            for (int j = 0; j < 4; ++j) av[r][j] = 0.f;

        // s-part: out[o] = sum_k acc[k] * W20[k][o]
#pragma unroll
        for (int r = 0; r < 2; ++r) {
            int o = l + r * 32;
#pragma unroll 4
            for (int k = 0; k < 96; k += 4) {
                float w0 = sW20[(k + 0) * 64 + o];
                float w1 = sW20[(k + 1) * 64 + o];
                float w2 = sW20[(k + 2) * 64 + o];
                float w3 = sW20[(k + 3) * 64 + o];
#pragma unroll
                for (int j = 0; j < 4; ++j) {
                    float4 a4 = *reinterpret_cast<const float4*>(acc + j * 480 + k);
                    as[r][j] += a4.x * w0 + a4.y * w1 + a4.z * w2 + a4.w * w3;
                }
            }
        }
        // v-part: out[u',c] = sum_u acc[96 + c*128 + u] * W21[u][u']
#pragma unroll
        for (int r = 0; r < 3; ++r) {
            int o = l + r * 32;
            int up = o / 3, c = o - up * 3;
            int abase = 96 + c * 128;
#pragma unroll 4
            for (int u = 0; u < 128; u += 4) {
                float w0 = sW21[(u + 0) * 32 + up];
                float w1 = sW21[(u + 1) * 32 + up];
                float w2 = sW21[(u + 2) * 32 + up];
                float w3 = sW21[(u + 3) * 32 + up];
#pragma unroll
                for (int j = 0; j < 4; ++j) {
                    float4 a4 = *reinterpret_cast<const float4*>(acc + j * 480 + abase + u);
                    av[r][j] += a4.x * w0 + a4.y * w1 + a4.z * w2 + a4.w * w3;
                }
            }
        }

        // finalize each node: skip, RMS, store
#pragma unroll
        for (int j = 0; j < 4; ++j) {
            int n = min(nb + j, NN - 1);
            float vs[2], vv[3];
            float ssq_s = 0.f, ssq_v = 0.f;
#pragma unroll
            for (int r = 0; r < 2; ++r) {
                int o = l + r * 32;
                float val = as[r][j] * 0.1020620726f + gss[(size_t)n * 64 + o];
                vs[r] = val;
                ssq_s += val * val;
            }
#pragma unroll
            for (int r = 0; r < 3; ++r) {
                int o = l + r * 32;
                float val = av[r][j] * 0.0883883476f + gsv[(size_t)n * 96 + o];
                vv[r] = val;
                ssq_v += val * val;
            }
#pragma unroll
            for (int d = 16; d; d >>= 1) {
                ssq_s += __shfl_xor_sync(0xffffffffu, ssq_s, d);
                ssq_v += __shfl_xor_sync(0xffffffffu, ssq_v, d);
            }
            if (nb + j < NN) {
                float rs = rsqrtf(ssq_s * (1.0f / 64.0f) + 1e-5f);
                float rv = rsqrtf(ssq_v * (1.0f / 32.0f) + 1e-5f);
#pragma unroll
                for (int r = 0; r < 2; ++r) {
                    int o = l + r * 32;
                    out[(size_t)n * 160 + o] = vs[r] * rs * sG[o];
                }
#pragma unroll
                for (int r = 0; r < 3; ++r) {
                    int o = l + r * 32;
                    out[(size_t)n * 160 + 64 + o] = vv[r] * rv * sG[64 + o / 3];
                }
            }
        }
        __syncwarp();
    }
}

// ---------------- launch ----------------
extern "C" void kernel_launch(void* const* d_in, const int* in_sizes, int n_in,
                              void* d_out, int out_size) {
    const float* nh    = (const float*)d_in[0];
    const int*   ei    = (const int*)  d_in[1];
    const float* esh   = (const float*)d_in[2];
    const float* eattr = (const float*)d_in[3];
    const float* W1_0  = (const float*)d_in[4];
    const float* W1_1  = (const float*)d_in[5];
    const float* Wfc1  = (const float*)d_in[6];
    const float* Wfc2  = (const float*)d_in[7];
    const float* Wfc3  = (const float*)d_in[8];
    const float* W2_0  = (const float*)d_in[9];
    const float* W2_1  = (const float*)d_in[10];
    const float* Wsc0  = (const float*)d_in[11];
    const float* Wsc1  = (const float*)d_in[12];
    const float* g0    = (const float*)d_in[13];
    const float* g1    = (const float*)d_in[14];
    float* out = (float*)d_out;

    cudaFuncSetAttribute(k_edge, cudaFuncAttributeMaxDynamicSharedMemorySize, 57344);
    cudaFuncSetAttribute(k_out, cudaFuncAttributeMaxDynamicSharedMemorySize, 103040);

    k_pre<<<11793, 256>>>(Wfc1, Wfc2, Wfc3);              // zero + transpose
    k_prep<<<391, 256>>>(nh, W1_0, W1_1, Wsc0, Wsc1);     // 64 nodes/block
    k_edge<<<3125, 128, 57344>>>(ei, esh, eattr);
    k_out<<<391, 256, 103040>>>(out, W2_0, W2_1, g0, g1); // 64 nodes/block
}